// round 16
// baseline (speedup 1.0000x reference)
#include <cuda_runtime.h>

using u64 = unsigned long long;

// ---------------- problem constants -----------------------------------------
constexpr int Bn = 4;
constexpr int Nn = 8192;
constexpr int M2 = 8192;
constexpr int M3 = 4096;
constexpr int M4 = 2048;
constexpr int MM = 4096;

constexpr int NB = 128;                 // 1D x bins, 1m wide
constexpr float XMIN = -64.f;
constexpr float WBIN = 1.0f;
constexpr float BIG  = 3.0e38f;
constexpr float MARG = 0.0625f;         // bound margin >> fp error of d
constexpr unsigned FULL = 0xFFFFFFFFu;
constexpr int TOTAL_ELEMS = Bn * (M2 + M3 + M4 + MM + Nn);   // 106496

constexpr int Q     = 2;                // queries per lane
constexpr int QPB   = 64;               // queries per block
constexpr int PARTS = 8;                // warps per block
constexpr int NT    = 256;

// padded group capacities per batch (elements padded to x4 per bin)
constexpr int CAPG2 = (M2 + 3 * NB) / 4;    // 2144 groups
constexpr int CAPG3 = (M3 + 3 * NB) / 4;    // 1120
constexpr int CAPG4 = (M4 + 3 * NB) / 4;    // 608
constexpr int CAPGM = (MM + 3 * NB) / 4;    // 1120

// ---------------- device scratch ---------------------------------------------
// geometry records per 4-cand group: [x4|y4|z4|kk4] = 64 B
__device__ __align__(16) float g2buf[Bn * CAPG2 * 16];
__device__ __align__(16) float g3buf[Bn * CAPG3 * 16];
__device__ __align__(16) float g4buf[Bn * CAPG4 * 16];
__device__ __align__(16) float gmbuf[Bn * CAPGM * 16];
// fv payloads, float4 per group (read only in the exact rescan)
__device__ __align__(16) float fv2buf[Bn * CAPG2 * 4];
__device__ __align__(16) float fv3buf[Bn * CAPG3 * 4];
__device__ __align__(16) float fv4buf[Bn * CAPG4 * 4];
// x-sorted queries
__device__ float qsx[Bn * Nn], qsy[Bn * Nn], qsz[Bn * Nn];
__device__ int   qsi[Bn * Nn];
__device__ int   gcnt[20 * NB];          // arr = set(0..2)*4+b | 12+b | 16+b
__device__ int   gfil[20 * NB];
__device__ int   goffs[20 * (NB + 1)];
__device__ float g_v[96];

// ---------------- packed f32x2 helpers ----------------------------------------
__device__ __forceinline__ u64 ffma2u(u64 a, u64 b, u64 c) {
    u64 r;
    asm("fma.rn.f32x2 %0, %1, %2, %3;" : "=l"(r) : "l"(a), "l"(b), "l"(c));
    return r;
}
__device__ __forceinline__ u64 fadd2u(u64 a, u64 b) {
    u64 r;
    asm("add.rn.f32x2 %0, %1, %2;" : "=l"(r) : "l"(a), "l"(b));
    return r;
}
__device__ __forceinline__ float lo_(u64 v) { return __uint_as_float((unsigned)v); }
__device__ __forceinline__ float hi_(u64 v) { return __uint_as_float((unsigned)(v >> 32)); }
__device__ __forceinline__ u64 dup2(float x) {
    unsigned b = __float_as_uint(x);
    return ((u64)b << 32) | (u64)b;
}
__device__ __forceinline__ int bin_of(float v) {
    int c = (int)(v - XMIN);
    return min(max(c, 0), NB - 1);
}

// ---------------- element decode ------------------------------------------------
__device__ __forceinline__ void decode(int idx, int& arr, int& il, int& flat) {
    if (idx < 32768)      { arr = (idx >> 13);           il = idx & 8191; flat = idx; }
    else if (idx < 49152) { int j = idx - 32768; arr = 4  + (j >> 12); il = j & 4095; flat = j; }
    else if (idx < 57344) { int j = idx - 49152; arr = 8  + (j >> 11); il = j & 2047; flat = j; }
    else if (idx < 73728) { int j = idx - 57344; arr = 12 + (j >> 12); il = j & 4095; flat = j; }
    else                  { int j = idx - 73728; arr = 16 + (j >> 13); il = j & 8191; flat = j; }
}
__device__ __forceinline__ const float* src_of(int arr,
    const float* k2, const float* k3, const float* k4,
    const float* mp, const float* pt)
{
    if (arr < 4)  return k2;
    if (arr < 8)  return k3;
    if (arr < 12) return k4;
    if (arr < 16) return mp;
    return pt;
}

// ---------------- K0: sentinel-init buffers + zero counters ----------------------
__global__ void init_kernel() {
    int i = blockIdx.x * 256 + threadIdx.x;
    constexpr int A = Bn * CAPG2;                 // 8576
    constexpr int B = A + Bn * CAPG3;             // 13056
    constexpr int C = B + Bn * CAPG4;             // 15488
    constexpr int D = C + Bn * CAPGM;             // 19968
    constexpr int E = D + 20 * NB;                // 22528
    const float4 z4 = make_float4(0.f, 0.f, 0.f, 0.f);
    const float4 s4 = make_float4(1e30f, 1e30f, 1e30f, 1e30f);
    if (i < D) {
        float* gp; float* fp = nullptr;
        if (i < A)      { gp = g2buf + (size_t)i * 16;       fp = fv2buf + (size_t)i * 4; }
        else if (i < B) { gp = g3buf + (size_t)(i - A) * 16; fp = fv3buf + (size_t)(i - A) * 4; }
        else if (i < C) { gp = g4buf + (size_t)(i - B) * 16; fp = fv4buf + (size_t)(i - B) * 4; }
        else            { gp = gmbuf + (size_t)(i - C) * 16; }
        float4* p = reinterpret_cast<float4*>(gp);
        p[0] = z4; p[1] = z4; p[2] = z4; p[3] = s4;     // kk=1e30 sentinels
        if (fp) *reinterpret_cast<float4*>(fp) = z4;
    } else if (i < E) {
        gcnt[i - D] = 0; gfil[i - D] = 0;
    }
}

// ---------------- K1: histogram + g_v ---------------------------------------------
__global__ void hist_kernel(const float* __restrict__ k2, const float* __restrict__ k3,
    const float* __restrict__ k4, const float* __restrict__ mp,
    const float* __restrict__ pt,
    const float* __restrict__ w_fc, const float* __restrict__ w_cls)
{
    int idx = blockIdx.x * 256 + threadIdx.x;
    if (blockIdx.x == 0 && threadIdx.x < 96) {
        float acc = 0.f;
#pragma unroll
        for (int k = 0; k < 64; k++)
            acc = fmaf(w_cls[k], w_fc[k * 96 + threadIdx.x], acc);
        g_v[threadIdx.x] = acc;
    }
    if (idx >= TOTAL_ELEMS) return;
    int arr, il, flat;
    decode(idx, arr, il, flat);
    const float* src = src_of(arr, k2, k3, k4, mp, pt);
    atomicAdd(&gcnt[arr * NB + bin_of(src[flat * 3])], 1);
}

// ---------------- K2: per-array exclusive prefix (padded counts) -------------------
__global__ void prefix_kernel() {
    int w = threadIdx.x >> 5, lane = threadIdx.x & 31;
    if (w >= 20) return;
    bool pad = (w < 16);
    int run = 0;
    for (int c0 = 0; c0 < NB; c0 += 32) {
        int bb = c0 + lane;
        int c = gcnt[w * NB + bb];
        if (pad) c = (c + 3) & ~3;
        int v = c;
#pragma unroll
        for (int o = 1; o < 32; o <<= 1) {
            int u = __shfl_up_sync(FULL, v, o);
            if (lane >= o) v += u;
        }
        goffs[w * (NB + 1) + bb] = run + v - c;
        run += __shfl_sync(FULL, v, 31);
    }
    if (lane == 0) goffs[w * (NB + 1) + NB] = run;
}

// ---------------- K3: scatter into padded binned records ---------------------------
__global__ void scatter_kernel(const float* __restrict__ k2, const float* __restrict__ f2,
    const float* __restrict__ k3, const float* __restrict__ f3,
    const float* __restrict__ k4, const float* __restrict__ f4,
    const float* __restrict__ mp, const float* __restrict__ pt)
{
    int idx = blockIdx.x * 256 + threadIdx.x;
    if (idx >= TOTAL_ELEMS) return;
    int arr, il, flat;
    decode(idx, arr, il, flat);
    const float* src = src_of(arr, k2, k3, k4, mp, pt);
    float x = src[flat * 3 + 0];
    float y = src[flat * 3 + 1];
    float z = src[flat * 3 + 2];
    // same rounding order as jnp.sum(p*p, -1)
    float kk = __fadd_rn(__fadd_rn(__fmul_rn(x, x), __fmul_rn(y, y)), __fmul_rn(z, z));
    int bb = bin_of(x);
    int pos = goffs[arr * (NB + 1) + bb] + atomicAdd(&gfil[arr * NB + bb], 1);
    int b = arr & 3;

    if (arr < 12) {
        const float* feats; int voff; float* buf; float* fvb; int capg;
        if (arr < 4)      { feats = f2; voff = 0;  buf = g2buf; fvb = fv2buf; capg = CAPG2; }
        else if (arr < 8) { feats = f3; voff = 32; buf = g3buf; fvb = fv3buf; capg = CAPG3; }
        else              { feats = f4; voff = 64; buf = g4buf; fvb = fv4buf; capg = CAPG4; }
        float acc = 0.f;
        const float4* fp = reinterpret_cast<const float4*>(feats + (size_t)flat * 32);
#pragma unroll
        for (int j = 0; j < 8; j++) {
            float4 t = fp[j];
            acc = fmaf(t.x, g_v[voff + 4 * j + 0], acc);
            acc = fmaf(t.y, g_v[voff + 4 * j + 1], acc);
            acc = fmaf(t.z, g_v[voff + 4 * j + 2], acc);
            acc = fmaf(t.w, g_v[voff + 4 * j + 3], acc);
        }
        int grp = b * capg + (pos >> 2);
        float* gp = buf + (size_t)grp * 16;
        int sl = pos & 3;
        gp[sl] = x; gp[4 + sl] = y; gp[8 + sl] = z; gp[12 + sl] = kk;
        fvb[grp * 4 + sl] = acc;
    } else if (arr < 16) {
        float* gp = gmbuf + (size_t)(b * CAPGM + (pos >> 2)) * 16;
        int sl = pos & 3;
        gp[sl] = x; gp[4 + sl] = y; gp[8 + sl] = z; gp[12 + sl] = kk;
    } else {
        int o = b * Nn + pos;
        qsx[o] = x; qsy[o] = y; qsz[o] = z;
        qsi[o] = b * Nn + il;                   // original global query index
    }
}

// ---------------- top-3 maintenance --------------------------------------------------
__device__ __forceinline__ void try_ins(float e, float fv, float t[3], float f[3]) {
    if (e < t[2]) {
        if (e < t[1]) {
            t[2] = t[1]; f[2] = f[1];
            if (e < t[0]) { t[1] = t[0]; f[1] = f[0]; t[0] = e; f[0] = fv; }
            else          { t[1] = e;    f[1] = fv; }
        } else { t[2] = e; f[2] = fv; }
    }
}
// caller guarantees e < m[2]
__device__ __forceinline__ void try_ins_g(float e, int g, float m[3], int gi[3]) {
    if (e < m[1]) {
        m[2] = m[1]; gi[2] = gi[1];
        if (e < m[0]) { m[1] = m[0]; gi[1] = gi[0]; m[0] = e; gi[0] = g; }
        else          { m[1] = e;    gi[1] = g; }
    } else { m[2] = e; gi[2] = g; }
}

// packed distances of one 64B group record; reference rounding order
__device__ __forceinline__ void group_d(const float* buf, int g,
    u64 c2x, u64 c2y, u64 c2z, u64 qq2,
    float& d0, float& d1, float& d2, float& d3)
{
    const ulonglong2* P = reinterpret_cast<const ulonglong2*>(buf) + (size_t)g * 4;
    ulonglong2 X = __ldg(P + 0);
    ulonglong2 Y = __ldg(P + 1);
    ulonglong2 Z = __ldg(P + 2);
    ulonglong2 W = __ldg(P + 3);
    u64 dl = fadd2u(qq2, W.x);
    dl = ffma2u(c2x, X.x, dl); dl = ffma2u(c2y, Y.x, dl); dl = ffma2u(c2z, Z.x, dl);
    u64 dh = fadd2u(qq2, W.y);
    dh = ffma2u(c2x, X.y, dh); dh = ffma2u(c2y, Y.y, dh); dh = ffma2u(c2z, Z.y, dh);
    d0 = lo_(dl); d1 = hi_(dl); d2 = lo_(dh); d3 = hi_(dh);
}

// hot loop body: group-min vs both queries (R13 verbatim semantics)
__device__ __forceinline__ void scan_group_min2(const float* buf, int g,
    const u64 c2x[Q], const u64 c2y[Q], const u64 c2z[Q], const u64 qq2[Q],
    float m[Q][3], int gi[Q][3])
{
    const ulonglong2* P = reinterpret_cast<const ulonglong2*>(buf) + (size_t)g * 4;
    ulonglong2 X = __ldg(P + 0);
    ulonglong2 Y = __ldg(P + 1);
    ulonglong2 Z = __ldg(P + 2);
    ulonglong2 W = __ldg(P + 3);
#pragma unroll
    for (int j = 0; j < Q; j++) {
        u64 dl = fadd2u(qq2[j], W.x);
        dl = ffma2u(c2x[j], X.x, dl);
        dl = ffma2u(c2y[j], Y.x, dl);
        dl = ffma2u(c2z[j], Z.x, dl);
        u64 dh = fadd2u(qq2[j], W.y);
        dh = ffma2u(c2x[j], X.y, dh);
        dh = ffma2u(c2y[j], Y.y, dh);
        dh = ffma2u(c2z[j], Z.y, dh);
        float mm = fminf(fminf(lo_(dl), hi_(dl)), fminf(lo_(dh), hi_(dh)));
        if (mm < m[j][2]) try_ins_g(mm, g, m[j], gi[j]);
    }
}

// ---------------- merge 24 partial top-3 entries -------------------------------
__device__ __forceinline__ float merge_one(const float2* __restrict__ ent) {
    float t[3] = {BIG, BIG, BIG}, f[3] = {0.f, 0.f, 0.f};
#pragma unroll
    for (int k = 0; k < PARTS * 3; k++) {
        float2 c = ent[k];
        try_ins(c.x, c.y, t, f);
    }
    float d0 = fmaxf(t[0], 0.f);
    float d1 = fmaxf(t[1], 0.f);
    float d2 = fmaxf(t[2], 0.f);
    float r0 = 1.f / (d0 + 1e-8f);
    float r1 = 1.f / (d1 + 1e-8f);
    float r2 = 1.f / (d2 + 1e-8f);
    return fmaf(r0, f[0], fmaf(r1, f[1], r2 * f[2])) / (r0 + r1 + r2);
}

// ---------------- K4: block-coherent windowed scan ------------------------------
// 512 blocks; each block owns 64 x-adjacent (sorted) queries of one batch.
// Every warp holds the same 64 queries -> block-uniform window; 8 warps
// stride-partition the window's groups with warp-broadcast loads.
__global__ void __launch_bounds__(NT, 4)
scan_fused(float* __restrict__ out) {
    __shared__ float2 s_m[QPB * PARTS * 3];      // 12 KB merge entries
    __shared__ float  s_mp[QPB * PARTS];         // 2 KB partial m2 publish

    const int tid   = threadIdx.x;
    const int qslot = tid & 31;
    const int part  = tid >> 5;
    const int b     = blockIdx.x >> 7;           // 128 blocks per batch
    const int qbase = b * Nn + (blockIdx.x & 127) * QPB;

    float xq[Q];
    u64 c2x[Q], c2y[Q], c2z[Q], qq2[Q];
#pragma unroll
    for (int j = 0; j < Q; j++) {
        int q = qbase + 2 * qslot + j;
        float x = qsx[q], y = qsy[q], z = qsz[q];
        xq[j] = x;
        float qq = __fadd_rn(__fadd_rn(__fmul_rn(x, x), __fmul_rn(y, y)),
                             __fmul_rn(z, z));
        c2x[j] = dup2(-2.f * x);
        c2y[j] = dup2(-2.f * y);
        c2z[j] = dup2(-2.f * z);
        qq2[j] = dup2(qq);
    }
    // warp-shared (and block-identical) x range of the 64 queries
    float wlo = fminf(xq[0], xq[1]);
    float whi = fmaxf(xq[0], xq[1]);
#pragma unroll
    for (int o = 16; o; o >>= 1) {
        wlo = fminf(wlo, __shfl_xor_sync(FULL, wlo, o));
        whi = fmaxf(whi, __shfl_xor_sync(FULL, whi, o));
    }
    const int B0 = bin_of(wlo), B1 = bin_of(whi);

    float pred = 0.f;                            // meaningful for tid < QPB
    const float* sb[3]  = { g2buf, g3buf, g4buf };
    const float* sfv[3] = { fv2buf, fv3buf, fv4buf };
    const int    caps[3] = { CAPG2, CAPG3, CAPG4 };

#pragma unroll 1
    for (int s = 0; s < 3; s++) {
        const float* buf = sb[s];
        const int* offs = goffs + (s * 4 + b) * (NB + 1);
        const int gb0 = b * caps[s];

        float m[Q][3]; int gi[Q][3];
#pragma unroll
        for (int j = 0; j < Q; j++) {
            m[j][0] = m[j][1] = m[j][2] = BIG;
            gi[j][0] = gi[j][1] = gi[j][2] = -1;
        }

        int bl = max(B0 - 1, 0), bh = min(B1 + 1, NB - 1);
        {
            int glo = gb0 + (__ldg(offs + bl) >> 2);
            int ghi = gb0 + (__ldg(offs + bh + 1) >> 2);
            for (int g = glo + part; g < ghi; g += PARTS)
                scan_group_min2(buf, g, c2x, c2y, c2z, qq2, m, gi);
        }
        // block-uniform expansion with per-round cross-part bound refresh
        while (true) {
            __syncthreads();
            s_mp[(2 * qslot + 0) * PARTS + part] = m[0][2];
            s_mp[(2 * qslot + 1) * PARTS + part] = m[1][2];
            __syncthreads();
            bool nL = false, nR = false;
            float eL = XMIN + bl * WBIN;         // unscanned left: x <= eL
            float eR = XMIN + (bh + 1) * WBIN;   // unscanned right: x >= eR
#pragma unroll
            for (int j = 0; j < Q; j++) {
                float tq = BIG;
#pragma unroll
                for (int p = 0; p < PARTS; p++)
                    tq = fminf(tq, s_mp[(2 * qslot + j) * PARTS + p]);
                float dL = xq[j] - eL, dR = eR - xq[j];
                if (bl > 0 && dL * dL < tq + MARG) nL = true;
                if (bh < NB - 1 && dR * dR < tq + MARG) nR = true;
            }
            unsigned mLb = __ballot_sync(FULL, nL);   // identical in every warp
            unsigned mRb = __ballot_sync(FULL, nR);
            if (!mLb && !mRb) break;
            if (mLb) {
                bl--;
                int glo = gb0 + (__ldg(offs + bl) >> 2);
                int ghi = gb0 + (__ldg(offs + bl + 1) >> 2);
                for (int g = glo + part; g < ghi; g += PARTS)
                    scan_group_min2(buf, g, c2x, c2y, c2z, qq2, m, gi);
            }
            if (mRb) {
                bh++;
                int glo = gb0 + (__ldg(offs + bh) >> 2);
                int ghi = gb0 + (__ldg(offs + bh + 1) >> 2);
                for (int g = glo + part; g < ghi; g += PARTS)
                    scan_group_min2(buf, g, c2x, c2y, c2z, qq2, m, gi);
            }
        }

        // exact rescan of the <=3 winning groups per query (bit-identical math)
        const float4* fv4 = reinterpret_cast<const float4*>(sfv[s]);
#pragma unroll
        for (int j = 0; j < Q; j++) {
            float t[3] = {BIG, BIG, BIG}, f[3] = {0.f, 0.f, 0.f};
#pragma unroll
            for (int k = 0; k < 3; k++) {
                int gg = gi[j][k];
                if (gg >= 0) {
                    float d0, d1, d2, d3;
                    group_d(buf, gg, c2x[j], c2y[j], c2z[j], qq2[j], d0, d1, d2, d3);
                    float4 F = __ldg(fv4 + gg);
                    try_ins(d0, F.x, t, f);
                    try_ins(d1, F.y, t, f);
                    try_ins(d2, F.z, t, f);
                    try_ins(d3, F.w, t, f);
                }
            }
            int q = 2 * qslot + j;
            int bse = (q * PARTS + part) * 3;
            s_m[bse + 0] = make_float2(t[0], f[0]);
            s_m[bse + 1] = make_float2(t[1], f[1]);
            s_m[bse + 2] = make_float2(t[2], f[2]);
        }
        __syncthreads();
        if (tid < QPB) pred += merge_one(s_m + tid * PARTS * 3);
        __syncthreads();
    }

    // ---- mask: any(d2 < 0.25) over fixed window [B0-1, B1+1] (1m margin > 0.5m) ----
    bool found[Q] = { false, false };
    {
        const int* offs = goffs + (12 + b) * (NB + 1);
        const int gb0 = b * CAPGM;
        int bl = max(B0 - 1, 0), bh = min(B1 + 1, NB - 1);
        int glo = gb0 + (__ldg(offs + bl) >> 2);
        int ghi = gb0 + (__ldg(offs + bh + 1) >> 2);
        float tf[Q], qxv[Q], qyv[Q], qzv[Q], qqv[Q];
#pragma unroll
        for (int j = 0; j < Q; j++) {
            qqv[j] = lo_(qq2[j]);
            tf[j]  = 0.3125f - qqv[j];           // e < 0.25 + 0.0625 margin
            qxv[j] = -0.5f * lo_(c2x[j]);        // exact (pow2 scale)
            qyv[j] = -0.5f * lo_(c2y[j]);
            qzv[j] = -0.5f * lo_(c2z[j]);
        }
        for (int g = glo + part; g < ghi; g += PARTS) {
            const ulonglong2* P = reinterpret_cast<const ulonglong2*>(gmbuf) + (size_t)g * 4;
            ulonglong2 X = __ldg(P + 0);
            ulonglong2 Y = __ldg(P + 1);
            ulonglong2 Z = __ldg(P + 2);
            ulonglong2 W = __ldg(P + 3);
#pragma unroll
            for (int j = 0; j < Q; j++) {
                // fast path: e = kk - 2*dot (qq deferred; protected by margin)
                u64 el = ffma2u(c2x[j], X.x, ffma2u(c2y[j], Y.x, ffma2u(c2z[j], Z.x, W.x)));
                u64 eh = ffma2u(c2x[j], X.y, ffma2u(c2y[j], Y.y, ffma2u(c2z[j], Z.y, W.y)));
                float mm = fminf(fminf(lo_(el), hi_(el)), fminf(lo_(eh), hi_(eh)));
                if (mm < tf[j]) {                 // rare: exact recheck
                    float cx[4] = { lo_(X.x), hi_(X.x), lo_(X.y), hi_(X.y) };
                    float cy[4] = { lo_(Y.x), hi_(Y.x), lo_(Y.y), hi_(Y.y) };
                    float cz[4] = { lo_(Z.x), hi_(Z.x), lo_(Z.y), hi_(Z.y) };
                    float cw[4] = { lo_(W.x), hi_(W.x), lo_(W.y), hi_(W.y) };
#pragma unroll
                    for (int c = 0; c < 4; c++) {
                        // bit-exact reference-mimic rounding
                        float dot = __fadd_rn(__fadd_rn(__fmul_rn(qxv[j], cx[c]),
                                                        __fmul_rn(qyv[j], cy[c])),
                                              __fmul_rn(qzv[j], cz[c]));
                        float d = __fsub_rn(__fadd_rn(qqv[j], cw[c]),
                                            __fadd_rn(dot, dot));
                        if (d < 0.25f) found[j] = true;
                    }
                }
            }
        }
    }

    float* s_fl = reinterpret_cast<float*>(s_m);
#pragma unroll
    for (int j = 0; j < Q; j++)
        s_fl[(2 * qslot + j) * PARTS + part] = found[j] ? 1.f : 0.f;
    __syncthreads();
    if (tid < QPB) {
        float fl = 0.f;
#pragma unroll
        for (int k = 0; k < PARTS; k++) fl = fmaxf(fl, s_fl[tid * PARTS + k]);
        int oi = qsi[qbase + tid];               // original query index
        out[oi] = pred;                          // pred_hm (B,N,1)
        out[Bn * Nn + oi] = fl;                  // gt_hm   (B,N)
    }
}

// ---------------- launch ---------------------------------------------------------------
extern "C" void kernel_launch(void* const* d_in, const int* in_sizes, int n_in,
                              void* d_out, int out_size) {
    (void)in_sizes; (void)n_in; (void)out_size;
    const float* pts    = (const float*)d_in[0];
    const float* known2 = (const float*)d_in[1];
    const float* feats2 = (const float*)d_in[2];
    const float* known3 = (const float*)d_in[3];
    const float* feats3 = (const float*)d_in[4];
    const float* known4 = (const float*)d_in[5];
    const float* feats4 = (const float*)d_in[6];
    const float* matchp = (const float*)d_in[7];
    const float* w_fc   = (const float*)d_in[8];
    const float* w_cls  = (const float*)d_in[9];
    float* out = (float*)d_out;

    constexpr int INIT_N = Bn * (CAPG2 + CAPG3 + CAPG4 + CAPGM) + 20 * NB;
    const int eb = (TOTAL_ELEMS + 255) / 256;
    init_kernel<<<(INIT_N + 255) / 256, 256>>>();
    hist_kernel<<<eb, 256>>>(known2, known3, known4, matchp, pts, w_fc, w_cls);
    prefix_kernel<<<1, 640>>>();
    scatter_kernel<<<eb, 256>>>(known2, feats2, known3, feats3,
                                known4, feats4, matchp, pts);
    scan_fused<<<(Bn * Nn) / QPB, NT>>>(out);    // 512 blocks, one wave
}